// round 2
// baseline (speedup 1.0000x reference)
#include <cuda_runtime.h>

// Problem constants (fixed by reference setup)
#define RQf 5.0f
#define THRESHOLDf 4.0f
#define RADIUS2f 100.0f   // (2*RQ)^2

typedef unsigned long long u64;

constexpr int Q       = 960;        // 4*6*40 query points
constexpr int M       = 50000;      // terrain points
constexpr int QB      = 8;          // queries per block (register-blocked)
constexpr int NQB     = Q / QB;     // 120
constexpr int MCHUNK  = 4;          // terrain chunks (grid.y) -> 480 blocks, single wave
constexpr int CHUNK   = M / MCHUNK; // 12500
constexpr int THREADS = 256;
constexpr int NWARP   = THREADS / 32;
constexpr int BP      = 24;         // output elements (B*P)
constexpr int T       = 40;         // trajectory length per (B,P)
constexpr int NBLOCKS = NQB * MCHUNK;

// Scratch partials: fully rewritten every launch -> deterministic, graph-safe.
__device__ float g_cnt[Q * MCHUNK];
__device__ float g_sum[Q * MCHUNK];
__device__ unsigned g_done = 0;

// ---- Blackwell packed fp32x2 helpers (FADD2/FMUL2/FFMA2 in SASS) ----
__device__ __forceinline__ u64 pack2(float lo, float hi) {
    u64 r; asm("mov.b64 %0, {%1, %2};" : "=l"(r) : "f"(lo), "f"(hi)); return r;
}
__device__ __forceinline__ void unpack2(u64 v, float& lo, float& hi) {
    asm("mov.b64 {%0, %1}, %2;" : "=f"(lo), "=f"(hi) : "l"(v));
}
__device__ __forceinline__ u64 add2(u64 a, u64 b) {
    u64 r; asm("add.rn.f32x2 %0, %1, %2;" : "=l"(r) : "l"(a), "l"(b)); return r;
}
__device__ __forceinline__ u64 mul2(u64 a, u64 b) {
    u64 r; asm("mul.rn.f32x2 %0, %1, %2;" : "=l"(r) : "l"(a), "l"(b)); return r;
}
__device__ __forceinline__ u64 fma2(u64 a, u64 b, u64 c) {
    u64 r; asm("fma.rn.f32x2 %0, %1, %2, %3;" : "=l"(r) : "l"(a), "l"(b), "l"(c)); return r;
}

__device__ __forceinline__ void accum(float d2, float& cnt, float& sum) {
    // Classification via exact d2 compare (matches reference fp32 rounding);
    // approx sqrt feeds only the sum (rel err ~1e-7 << 1e-3 gate).
    float d;
    asm("sqrt.approx.f32 %0, %1;" : "=f"(d) : "f"(d2));
    if (d2 <= RADIUS2f) { cnt += 1.0f; sum += d; }
}

__global__ __launch_bounds__(THREADS, 4)
void fused_kernel(const float* __restrict__ q, const float* __restrict__ terr,
                  float* __restrict__ out) {
    const int qb = blockIdx.x;   // 0..NQB-1
    const int mc = blockIdx.y;   // 0..MCHUNK-1
    const int q0 = qb * QB;
    const int tid = threadIdx.x;

    // Negated query coords, packed in pairs (so dx^2 == (t - q)^2 via add2).
    u64 nqx[QB / 2], nqy[QB / 2], nqz[QB / 2];
#pragma unroll
    for (int j2 = 0; j2 < QB / 2; j2++) {
        const int ja = q0 + 2 * j2, jb = ja + 1;
        nqx[j2] = pack2(-__ldg(q + ja * 3 + 0), -__ldg(q + jb * 3 + 0));
        nqy[j2] = pack2(-__ldg(q + ja * 3 + 1), -__ldg(q + jb * 3 + 1));
        nqz[j2] = pack2(-__ldg(q + ja * 3 + 2), -__ldg(q + jb * 3 + 2));
    }

    float cnt[QB], sum[QB];
#pragma unroll
    for (int j = 0; j < QB; j++) { cnt[j] = 0.f; sum[j] = 0.f; }

    const int mstart = mc * CHUNK;
    const int mend   = mstart + CHUNK;
    for (int i = mstart + tid; i < mend; i += THREADS) {
        const u64 txp = pack2(__ldg(terr + 3 * i + 0), __ldg(terr + 3 * i + 0));
        const u64 typ = pack2(__ldg(terr + 3 * i + 1), __ldg(terr + 3 * i + 1));
        const u64 tzp = pack2(__ldg(terr + 3 * i + 2), __ldg(terr + 3 * i + 2));
#pragma unroll
        for (int j2 = 0; j2 < QB / 2; j2++) {
            const u64 dx = add2(nqx[j2], txp);
            const u64 dy = add2(nqy[j2], typ);
            const u64 dz = add2(nqz[j2], tzp);
            u64 d2p = mul2(dx, dx);
            d2p = fma2(dy, dy, d2p);
            d2p = fma2(dz, dz, d2p);
            float d2a, d2b;
            unpack2(d2p, d2a, d2b);
            accum(d2a, cnt[2 * j2 + 0], sum[2 * j2 + 0]);
            accum(d2b, cnt[2 * j2 + 1], sum[2 * j2 + 1]);
        }
    }

    // Intra-warp tree reduce (per query slot)
#pragma unroll
    for (int j = 0; j < QB; j++) {
#pragma unroll
        for (int off = 16; off > 0; off >>= 1) {
            cnt[j] += __shfl_down_sync(0xffffffffu, cnt[j], off);
            sum[j] += __shfl_down_sync(0xffffffffu, sum[j], off);
        }
    }

    __shared__ float s_cnt[NWARP][QB];
    __shared__ float s_sum[NWARP][QB];
    const int lane = tid & 31;
    const int wid  = tid >> 5;
    if (lane == 0) {
#pragma unroll
        for (int j = 0; j < QB; j++) { s_cnt[wid][j] = cnt[j]; s_sum[wid][j] = sum[j]; }
    }
    __syncthreads();
    if (tid < QB) {
        float c = 0.f, s = 0.f;
#pragma unroll
        for (int w = 0; w < NWARP; w++) { c += s_cnt[w][tid]; s += s_sum[w][tid]; }
        g_cnt[(q0 + tid) * MCHUNK + mc] = c;
        g_sum[(q0 + tid) * MCHUNK + mc] = s;
    }
    __threadfence();
    __syncthreads();

    // Last-block finalize (deterministic: single block, fixed order).
    __shared__ bool s_last;
    if (tid == 0) {
        const unsigned ticket = atomicAdd(&g_done, 1u);
        s_last = (ticket == (unsigned)(NBLOCKS - 1));
    }
    __syncthreads();
    if (!s_last) return;

    __shared__ float s_pp[Q];
    for (int qi = tid; qi < Q; qi += THREADS) {
        float c = 0.f, s = 0.f;
#pragma unroll
        for (int m2 = 0; m2 < MCHUNK; m2++) {
            c += g_cnt[qi * MCHUNK + m2];
            s += g_sum[qi * MCHUNK + m2];
        }
        float pp = 0.f;
        if (c > 0.f) {
            const float dm = s / c;
            pp = -(dm * dm) * (1.0f / (RQf * RQf)) + THRESHOLDf;
        }
        s_pp[qi] = pp;
    }
    __syncthreads();
    if (tid < BP) {
        float acc = 0.f;
#pragma unroll
        for (int t = 0; t < T; t++) acc += s_pp[tid * T + t];
        out[tid] = acc;
    }
    if (tid == 0) g_done = 0;  // reset for next graph replay
}

extern "C" void kernel_launch(void* const* d_in, const int* in_sizes, int n_in,
                              void* d_out, int out_size) {
    // Inputs per metadata order: [traj (960*3), terrain (50000*3)].
    const float* qptr = (const float*)d_in[0];
    const float* tptr = (const float*)d_in[1];
    if (n_in >= 2 && in_sizes[0] == M * 3 && in_sizes[1] == Q * 3) {
        const float* tmp = qptr; qptr = tptr; tptr = tmp;
    }
    float* out = (float*)d_out;

    dim3 grid(NQB, MCHUNK);
    fused_kernel<<<grid, THREADS>>>(qptr, tptr, out);
}

// round 3
// speedup vs baseline: 1.1611x; 1.1611x over previous
#include <cuda_runtime.h>

// Problem constants (fixed by reference setup)
#define RADIUS2f 100.0f            // (2*RQ)^2
#define PRUNE2f  100.001f          // AABB prune with fp-rounding margin

constexpr int M   = 50000;         // terrain points
constexpr int Q   = 960;           // 4*6*40 query points
constexpr int BP  = 24;            // output elements (B*P)
constexpr int T   = 40;            // trajectory length per (B,P)

constexpr int   GN       = 10;     // grid cells per dim (cell edge == radius)
constexpr float INV_CELL = 0.1f;
constexpr float CELLW    = 10.0f;
constexpr int   NCELL    = GN * GN * GN;   // 1000
constexpr int   CAP      = 128;            // Poisson(50) -> overflow ~1e-19

constexpr int NT   = 512;          // threads per block (16 warps)
constexpr int NWPB = NT / 32;

// Scratch (static __device__ = allowed). Counters zero at module load and are
// reset by each call's finalize -> deterministic across graph replays.
__device__ int      g_cellcnt[NCELL];
__device__ float4   g_cellpts[NCELL * CAP];
__device__ float2   g_part[Q * 2];         // (cnt, sum) per query-half
__device__ unsigned g_bar  = 0;
__device__ unsigned g_tick = 0;

__global__ __launch_bounds__(NT, 1)
void fused(const float* __restrict__ qg, const float* __restrict__ terr,
           float* __restrict__ out, int nb) {
    const int tid = threadIdx.x;
    const int b   = blockIdx.x;

    // ---------- Phase 1: bin terrain into 10x10x10 grid ----------
    for (int i = b * NT + tid; i < M; i += nb * NT) {
        const float x = __ldg(terr + 3 * i + 0);
        const float y = __ldg(terr + 3 * i + 1);
        const float z = __ldg(terr + 3 * i + 2);
        const int cx = min(GN - 1, max(0, (int)(x * INV_CELL)));
        const int cy = min(GN - 1, max(0, (int)(y * INV_CELL)));
        const int cz = min(GN - 1, max(0, (int)(z * INV_CELL)));
        const int c  = (cz * GN + cy) * GN + cx;
        const int slot = atomicAdd(&g_cellcnt[c], 1);
        if (slot < CAP) g_cellpts[c * CAP + slot] = make_float4(x, y, z, 0.f);
    }

    // ---------- Grid barrier (single wave: nb blocks, 1/SM resident) ----------
    __threadfence();
    __syncthreads();
    if (tid == 0) {
        atomicAdd(&g_bar, 1u);
        while (*(volatile unsigned*)&g_bar < (unsigned)nb) { }
    }
    __syncthreads();
    __threadfence();   // acquire: bins visible to all readers

    // ---------- Phase 2: warp-pair per query (parity split of 27 cells) ----------
    const int w    = tid >> 5;
    const int lane = tid & 31;
    for (int gw = b + nb * w; gw < 2 * Q; gw += nb * NWPB) {
        const int qi   = gw >> 1;
        const int half = gw & 1;

        const float qx = __ldg(qg + 3 * qi + 0);
        const float qy = __ldg(qg + 3 * qi + 1);
        const float qz = __ldg(qg + 3 * qi + 2);
        const int cx = min(GN - 1, max(0, (int)(qx * INV_CELL)));
        const int cy = min(GN - 1, max(0, (int)(qy * INV_CELL)));
        const int cz = min(GN - 1, max(0, (int)(qz * INV_CELL)));

        float cnt = 0.f, sum = 0.f;
        int cellidx = 0;
        for (int zz = max(cz - 1, 0); zz <= min(cz + 1, GN - 1); zz++)
        for (int yy = max(cy - 1, 0); yy <= min(cy + 1, GN - 1); yy++)
        for (int xx = max(cx - 1, 0); xx <= min(cx + 1, GN - 1); xx++, cellidx++) {
            if ((cellidx & 1) != half) continue;

            // AABB min-distance^2 prune (margin covers fp rounding)
            const float lx = xx * CELLW, ly = yy * CELLW, lz = zz * CELLW;
            const float ex = fmaxf(fmaxf(lx - qx, qx - (lx + CELLW)), 0.f);
            const float ey = fmaxf(fmaxf(ly - qy, qy - (ly + CELLW)), 0.f);
            const float ez = fmaxf(fmaxf(lz - qz, qz - (lz + CELLW)), 0.f);
            if (fmaf(ez, ez, fmaf(ey, ey, ex * ex)) > PRUNE2f) continue;

            const int c = (zz * GN + yy) * GN + xx;
            const int n = min(g_cellcnt[c], CAP);
            const float4* __restrict__ pts = g_cellpts + c * CAP;
            for (int k = lane; k < n; k += 32) {
                const float4 p = pts[k];
                const float dx = qx - p.x, dy = qy - p.y, dz = qz - p.z;
                const float d2 = fmaf(dz, dz, fmaf(dy, dy, dx * dx));
                // Exact-d2 classification (validated R1/R2); approx sqrt feeds
                // only the sum (rel err ~1e-7 << 1e-3 gate).
                float d;
                asm("sqrt.approx.f32 %0, %1;" : "=f"(d) : "f"(d2));
                if (d2 <= RADIUS2f) { cnt += 1.f; sum += d; }
            }
        }

#pragma unroll
        for (int off = 16; off > 0; off >>= 1) {
            cnt += __shfl_down_sync(0xffffffffu, cnt, off);
            sum += __shfl_down_sync(0xffffffffu, sum, off);
        }
        if (lane == 0) g_part[gw] = make_float2(cnt, sum);
    }

    // ---------- Ticket: last block finalizes + resets ----------
    __threadfence();
    __syncthreads();
    __shared__ bool s_last;
    if (tid == 0) s_last = (atomicAdd(&g_tick, 1u) == (unsigned)(nb - 1));
    __syncthreads();
    if (!s_last) return;
    __threadfence();

    if (tid < BP) {
        float acc = 0.f;
#pragma unroll 4
        for (int t = 0; t < T; t++) {
            const int qi = tid * T + t;
            const float2 a = g_part[2 * qi + 0];
            const float2 bb = g_part[2 * qi + 1];
            const float c = a.x + bb.x;
            const float s = a.y + bb.y;
            if (c > 0.f) {
                const float dm = s / c;
                acc += -(dm * dm) * 0.04f + 4.0f;   // -(dm^2)/RQ^2 + THRESHOLD
            }
        }
        out[tid] = acc;
    }
    // Reset scratch for the next graph replay
    for (int i = tid; i < NCELL; i += NT) g_cellcnt[i] = 0;
    if (tid == 0) { g_bar = 0; g_tick = 0; }
}

extern "C" void kernel_launch(void* const* d_in, const int* in_sizes, int n_in,
                              void* d_out, int out_size) {
    // Inputs per metadata order: [traj (960*3), terrain (50000*3)].
    const float* qptr = (const float*)d_in[0];
    const float* tptr = (const float*)d_in[1];
    if (n_in >= 2 && in_sizes[0] == M * 3 && in_sizes[1] == Q * 3) {
        const float* tmp = qptr; qptr = tptr; tptr = tmp;
    }
    float* out = (float*)d_out;

    int nb = 148;
    cudaDeviceGetAttribute(&nb, cudaDevAttrMultiProcessorCount, 0);
    if (nb > 148) nb = 148;   // one wave max; barrier requires full residency

    fused<<<nb, NT>>>(qptr, tptr, out, nb);
}

// round 4
// speedup vs baseline: 1.8129x; 1.5613x over previous
#include <cuda_runtime.h>

// Problem constants (fixed by reference setup)
#define RADIUS2f 100.0f            // (2*RQ)^2
#define PRUNE2f  100.001f          // AABB prune with fp-rounding margin

constexpr int M   = 50000;         // terrain points
constexpr int Q   = 960;           // 4*6*40 query points
constexpr int BP  = 24;            // output elements (B*P)
constexpr int T   = 40;            // trajectory length per (B,P)

constexpr int   GN       = 10;     // grid cells per dim (cell edge == radius)
constexpr float INV_CELL = 0.1f;
constexpr float CELLW    = 10.0f;
constexpr int   NCELL    = GN * GN * GN;   // 1000
constexpr int   CAP      = 128;            // Poisson(50) -> overflow ~1e-19

constexpr int SPLIT   = 4;                  // cell-quarters per query
constexpr int NWU     = Q * SPLIT;          // 3840 warp work units
constexpr int QNT     = 512;                // query kernel threads/block
constexpr int QNW     = QNT / 32;           // 16 warps/block
constexpr int QBLOCKS = NWU / QNW;          // 240 blocks

// Scratch: zero at module load; finalize resets for the next graph replay.
__device__ int      g_cellcnt[NCELL];
__device__ float4   g_cellpts[NCELL * CAP];
__device__ float2   g_part[NWU];            // (cnt, sum) per warp unit
__device__ unsigned g_tick = 0;

// ---------------- Kernel A: bin terrain into the 10^3 grid ----------------
__global__ __launch_bounds__(256)
void bin_kernel(const float* __restrict__ terr) {
    const int i = blockIdx.x * 256 + threadIdx.x;
    if (i >= M) return;
    const float x = __ldg(terr + 3 * i + 0);
    const float y = __ldg(terr + 3 * i + 1);
    const float z = __ldg(terr + 3 * i + 2);
    const int cx = min(GN - 1, max(0, (int)(x * INV_CELL)));
    const int cy = min(GN - 1, max(0, (int)(y * INV_CELL)));
    const int cz = min(GN - 1, max(0, (int)(z * INV_CELL)));
    const int c  = (cz * GN + cy) * GN + cx;
    const int slot = atomicAdd(&g_cellcnt[c], 1);
    if (slot < CAP) g_cellpts[c * CAP + slot] = make_float4(x, y, z, 0.f);
}

// ---------- Kernel B: query (warp per query-quarter) + ticket finalize ----------
__global__ __launch_bounds__(QNT)
void query_kernel(const float* __restrict__ qg, float* __restrict__ out) {
    const int tid  = threadIdx.x;
    const int lane = tid & 31;
    const int gw   = blockIdx.x * QNW + (tid >> 5);   // 0..NWU-1
    const int qi   = gw >> 2;
    const int quarter = gw & 3;

    const float qx = __ldg(qg + 3 * qi + 0);
    const float qy = __ldg(qg + 3 * qi + 1);
    const float qz = __ldg(qg + 3 * qi + 2);
    const int cx = min(GN - 1, max(0, (int)(qx * INV_CELL)));
    const int cy = min(GN - 1, max(0, (int)(qy * INV_CELL)));
    const int cz = min(GN - 1, max(0, (int)(qz * INV_CELL)));

    // Lane-parallel cell setup: lane l < 27 owns neighbor cell l.
    const int dx = lane % 3 - 1;
    const int dy = (lane / 3) % 3 - 1;
    const int dz = lane / 9 - 1;
    const int xx = cx + dx, yy = cy + dy, zz = cz + dz;
    bool valid = (lane < 27) && ((lane & 3) == quarter) &&
                 (unsigned)xx < (unsigned)GN && (unsigned)yy < (unsigned)GN &&
                 (unsigned)zz < (unsigned)GN;
    int c = 0, ncell = 0;
    if (valid) {
        // AABB min-distance^2 prune (margin covers fp rounding)
        const float lx = xx * CELLW, ly = yy * CELLW, lz = zz * CELLW;
        const float ex = fmaxf(fmaxf(lx - qx, qx - (lx + CELLW)), 0.f);
        const float ey = fmaxf(fmaxf(ly - qy, qy - (ly + CELLW)), 0.f);
        const float ez = fmaxf(fmaxf(lz - qz, qz - (lz + CELLW)), 0.f);
        if (fmaf(ez, ez, fmaf(ey, ey, ex * ex)) <= PRUNE2f) {
            c = (zz * GN + yy) * GN + xx;
            ncell = min(g_cellcnt[c], CAP);     // all surviving counts load in parallel
            if (ncell > 0) { } else valid = false;
        } else valid = false;
    }

    float cnt = 0.f, sum = 0.f;
    unsigned mask = __ballot_sync(0xffffffffu, valid);
    while (mask) {
        const int src = __ffs(mask) - 1;
        mask &= mask - 1;
        const int cc = __shfl_sync(0xffffffffu, c, src);
        const int n  = __shfl_sync(0xffffffffu, ncell, src);
        const float4* __restrict__ pts = g_cellpts + cc * CAP;
        for (int k = lane; k < n; k += 32) {
            const float4 p = pts[k];
            const float ddx = qx - p.x, ddy = qy - p.y, ddz = qz - p.z;
            const float d2 = fmaf(ddz, ddz, fmaf(ddy, ddy, ddx * ddx));
            // Exact-d2 classification (validated R1-R3); approx sqrt feeds
            // only the sum (rel err ~1.5e-7 << 1e-3 gate).
            float d;
            asm("sqrt.approx.f32 %0, %1;" : "=f"(d) : "f"(d2));
            if (d2 <= RADIUS2f) { cnt += 1.f; sum += d; }
        }
    }

#pragma unroll
    for (int off = 16; off > 0; off >>= 1) {
        cnt += __shfl_down_sync(0xffffffffu, cnt, off);
        sum += __shfl_down_sync(0xffffffffu, sum, off);
    }
    if (lane == 0) g_part[gw] = make_float2(cnt, sum);

    // ---------- Ticket: last block finalizes + resets ----------
    __threadfence();
    __syncthreads();
    __shared__ bool s_last;
    if (tid == 0) s_last = (atomicAdd(&g_tick, 1u) == (unsigned)(QBLOCKS - 1));
    __syncthreads();
    if (!s_last) return;
    __threadfence();

    __shared__ float s_pp[Q];
    for (int q2 = tid; q2 < Q; q2 += QNT) {
        const float2 p0 = g_part[4 * q2 + 0];
        const float2 p1 = g_part[4 * q2 + 1];
        const float2 p2 = g_part[4 * q2 + 2];
        const float2 p3 = g_part[4 * q2 + 3];
        const float cc = (p0.x + p1.x) + (p2.x + p3.x);
        const float ss = (p0.y + p1.y) + (p2.y + p3.y);
        float pp = 0.f;
        if (cc > 0.f) {
            const float dm = ss / cc;
            pp = -(dm * dm) * 0.04f + 4.0f;   // -(dm^2)/RQ^2 + THRESHOLD
        }
        s_pp[q2] = pp;
    }
    __syncthreads();
    if (tid < BP) {
        float acc = 0.f;
#pragma unroll 8
        for (int t = 0; t < T; t++) acc += s_pp[tid * T + t];
        out[tid] = acc;
    }
    // Reset scratch for the next graph replay
    for (int i = tid; i < NCELL; i += QNT) g_cellcnt[i] = 0;
    if (tid == 0) g_tick = 0;
}

extern "C" void kernel_launch(void* const* d_in, const int* in_sizes, int n_in,
                              void* d_out, int out_size) {
    // Inputs per metadata order: [traj (960*3), terrain (50000*3)].
    const float* qptr = (const float*)d_in[0];
    const float* tptr = (const float*)d_in[1];
    if (n_in >= 2 && in_sizes[0] == M * 3 && in_sizes[1] == Q * 3) {
        const float* tmp = qptr; qptr = tptr; tptr = tmp;
    }
    float* out = (float*)d_out;

    bin_kernel<<<(M + 255) / 256, 256>>>(tptr);
    query_kernel<<<QBLOCKS, QNT>>>(qptr, out);
}

// round 5
// speedup vs baseline: 1.8448x; 1.0176x over previous
#include <cuda_runtime.h>

// Problem constants (fixed by reference setup)
#define RADIUS2f 100.0f            // (2*RQ)^2
#define PRUNE2f  100.001f          // AABB prune with fp-rounding margin

constexpr int M   = 50000;         // terrain points
constexpr int Q   = 960;           // 4*6*40 query points
constexpr int BP  = 24;            // output elements (B*P)
constexpr int T   = 40;            // trajectory length per (B,P)

constexpr int   GN       = 10;     // grid cells per dim (cell edge == radius)
constexpr float INV_CELL = 0.1f;
constexpr float CELLW    = 10.0f;
constexpr int   NCELL    = GN * GN * GN;   // 1000
constexpr int   CAP      = 128;            // Poisson(50) -> overflow ~1e-19

constexpr int SPLIT   = 8;                  // cell-octants per query
constexpr int NWU     = Q * SPLIT;          // 7680 warp work units
constexpr int QNT     = 256;                // query kernel threads/block
constexpr int QNW     = QNT / 32;           // 8 warps/block
constexpr int QBLOCKS = NWU / QNW;          // 960 blocks

// Scratch: zero at module load; finalize resets for the next graph replay.
__device__ int      g_cellcnt[NCELL];
__device__ float4   g_cellpts[NCELL * CAP];
__device__ float2   g_part[NWU];            // (cnt, sum) per warp unit
__device__ unsigned g_tick = 0;

// ------- Kernel A: bin terrain (4 points/thread for atomic ILP) -------
__global__ __launch_bounds__(256)
void bin_kernel(const float4* __restrict__ terr4) {
    const int i = blockIdx.x * 256 + threadIdx.x;   // point-group index
    if (i >= M / 4) return;
    const float4 a = __ldg(terr4 + 3 * i + 0);      // p0.xyz p1.x
    const float4 b = __ldg(terr4 + 3 * i + 1);      // p1.yz  p2.xy
    const float4 c = __ldg(terr4 + 3 * i + 2);      // p2.z   p3.xyz
    float px[4] = {a.x, a.w, b.z, c.y};
    float py[4] = {a.y, b.x, b.w, c.z};
    float pz[4] = {a.z, b.y, c.x, c.w};
    int cell[4], slot[4];
#pragma unroll
    for (int j = 0; j < 4; j++) {
        const int cx = min(GN - 1, max(0, (int)(px[j] * INV_CELL)));
        const int cy = min(GN - 1, max(0, (int)(py[j] * INV_CELL)));
        const int cz = min(GN - 1, max(0, (int)(pz[j] * INV_CELL)));
        cell[j] = (cz * GN + cy) * GN + cx;
    }
#pragma unroll
    for (int j = 0; j < 4; j++) slot[j] = atomicAdd(&g_cellcnt[cell[j]], 1);
#pragma unroll
    for (int j = 0; j < 4; j++)
        if (slot[j] < CAP)
            g_cellpts[cell[j] * CAP + slot[j]] = make_float4(px[j], py[j], pz[j], 0.f);
}

// ------- Kernel B: query (warp per query-octant) + ticket finalize -------
__global__ __launch_bounds__(QNT)
void query_kernel(const float* __restrict__ qg, float* __restrict__ out) {
    const int tid  = threadIdx.x;
    const int lane = tid & 31;
    const int gw   = blockIdx.x * QNW + (tid >> 5);   // 0..NWU-1
    const int qi   = gw >> 3;
    const int oct  = gw & 7;

    const float qx = __ldg(qg + 3 * qi + 0);
    const float qy = __ldg(qg + 3 * qi + 1);
    const float qz = __ldg(qg + 3 * qi + 2);
    const int cx = min(GN - 1, max(0, (int)(qx * INV_CELL)));
    const int cy = min(GN - 1, max(0, (int)(qy * INV_CELL)));
    const int cz = min(GN - 1, max(0, (int)(qz * INV_CELL)));

    // Lane-parallel cell setup: lane l < 27 owns neighbor cell l; this warp
    // takes cells where (l & 7) == oct.
    const int dx = lane % 3 - 1;
    const int dy = (lane / 3) % 3 - 1;
    const int dz = lane / 9 - 1;
    const int xx = cx + dx, yy = cy + dy, zz = cz + dz;
    bool valid = (lane < 27) && ((lane & 7) == oct) &&
                 (unsigned)xx < (unsigned)GN && (unsigned)yy < (unsigned)GN &&
                 (unsigned)zz < (unsigned)GN;
    int c = 0, ncell = 0;
    if (valid) {
        // AABB min-distance^2 prune (margin covers fp rounding)
        const float lx = xx * CELLW, ly = yy * CELLW, lz = zz * CELLW;
        const float ex = fmaxf(fmaxf(lx - qx, qx - (lx + CELLW)), 0.f);
        const float ey = fmaxf(fmaxf(ly - qy, qy - (ly + CELLW)), 0.f);
        const float ez = fmaxf(fmaxf(lz - qz, qz - (lz + CELLW)), 0.f);
        if (fmaf(ez, ez, fmaf(ey, ey, ex * ex)) <= PRUNE2f) {
            c = (zz * GN + yy) * GN + xx;
            ncell = min(g_cellcnt[c], CAP);   // surviving counts load in parallel
            valid = (ncell > 0);
        } else valid = false;
    }

    float cnt = 0.f, sum = 0.f;
    unsigned mask = __ballot_sync(0xffffffffu, valid);
    while (mask) {
        const int src = __ffs(mask) - 1;
        mask &= mask - 1;
        const int cc = __shfl_sync(0xffffffffu, c, src);
        const int n  = __shfl_sync(0xffffffffu, ncell, src);
        const float4* __restrict__ pts = g_cellpts + cc * CAP;
        for (int k = lane; k < n; k += 32) {
            const float4 p = __ldg(pts + k);
            const float ddx = qx - p.x, ddy = qy - p.y, ddz = qz - p.z;
            const float d2 = fmaf(ddz, ddz, fmaf(ddy, ddy, ddx * ddx));
            // Exact-d2 classification (validated R1-R4); approx sqrt feeds
            // only the sum (rel err ~1.5e-7 << 1e-3 gate).
            float d;
            asm("sqrt.approx.f32 %0, %1;" : "=f"(d) : "f"(d2));
            if (d2 <= RADIUS2f) { cnt += 1.f; sum += d; }
        }
    }

#pragma unroll
    for (int off = 16; off > 0; off >>= 1) {
        cnt += __shfl_down_sync(0xffffffffu, cnt, off);
        sum += __shfl_down_sync(0xffffffffu, sum, off);
    }
    if (lane == 0) g_part[gw] = make_float2(cnt, sum);

    // ---------- Ticket: last block finalizes + resets ----------
    __threadfence();
    __syncthreads();
    __shared__ bool s_last;
    if (tid == 0) s_last = (atomicAdd(&g_tick, 1u) == (unsigned)(QBLOCKS - 1));
    __syncthreads();
    if (!s_last) return;
    __threadfence();

    __shared__ float s_pp[Q];
    for (int q2 = tid; q2 < Q; q2 += QNT) {
        float cc = 0.f, ss = 0.f;
#pragma unroll
        for (int j = 0; j < SPLIT; j++) {
            const float2 p = g_part[SPLIT * q2 + j];
            cc += p.x; ss += p.y;
        }
        float pp = 0.f;
        if (cc > 0.f) {
            const float dm = ss / cc;
            pp = -(dm * dm) * 0.04f + 4.0f;   // -(dm^2)/RQ^2 + THRESHOLD
        }
        s_pp[q2] = pp;
    }
    __syncthreads();
    if (tid < BP) {
        float acc = 0.f;
#pragma unroll 8
        for (int t = 0; t < T; t++) acc += s_pp[tid * T + t];
        out[tid] = acc;
    }
    // Reset scratch for the next graph replay
    for (int i = tid; i < NCELL; i += QNT) g_cellcnt[i] = 0;
    if (tid == 0) g_tick = 0;
}

extern "C" void kernel_launch(void* const* d_in, const int* in_sizes, int n_in,
                              void* d_out, int out_size) {
    // Inputs per metadata order: [traj (960*3), terrain (50000*3)].
    const float* qptr = (const float*)d_in[0];
    const float* tptr = (const float*)d_in[1];
    if (n_in >= 2 && in_sizes[0] == M * 3 && in_sizes[1] == Q * 3) {
        const float* tmp = qptr; qptr = tptr; tptr = tmp;
    }
    float* out = (float*)d_out;

    bin_kernel<<<(M / 4 + 255) / 256, 256>>>((const float4*)tptr);
    query_kernel<<<QBLOCKS, QNT>>>(qptr, out);
}